// round 3
// baseline (speedup 1.0000x reference)
#include <cuda_runtime.h>
#include <cuda_bf16.h>
#include <cstdint>

// out[v, t, n] = tlut[encoded[t, n], v]
// tlut:   (65536, 2) float32 -> contiguous float2 per entry (8B)
// encoded:(128, 262144) int32
// out:    (2, 128, 262144) float32
//
// L1tex-wavefront-bound gather. Hybrid LUT: first 28672 entries (224 KB,
// 43.75% of table) live in SMEM and are fetched via LDS (bank-parallel,
// ~3 wf/inst) instead of LDG (~1 wf per lane). Per-lane predicated
// ld.shared / ld.global pair in inline PTX (no BSSY/BSYNC divergence).

static constexpr long long TB_ = 128;
static constexpr long long N_  = 262144;
static constexpr long long TOTAL  = TB_ * N_;      // 33,554,432 per plane
static constexpr long long TOTAL4 = TOTAL / 4;     // 8,388,608 quads

static constexpr int SMEM_ENTRIES = 28672;                    // 224 KB of float2
static constexpr int SMEM_BYTES   = SMEM_ENTRIES * 8;         // 229376
static constexpr int NUM_CTAS     = 148;
static constexpr int NUM_THREADS  = 1024;

// Per-lane predicated gather: smem if e < SMEM_ENTRIES, else global (L1/L2).
__device__ __forceinline__ float2 gather_lut(int e, uint32_t smem_base,
                                             const float2* __restrict__ glut)
{
    float2 r;
    uint32_t saddr = smem_base + ((uint32_t)e << 3);
    const float2* gaddr = glut + e;
    asm volatile(
        "{\n\t"
        ".reg .pred p;\n\t"
        "setp.lt.s32 p, %2, %3;\n\t"
        "@p  ld.shared.v2.f32 {%0,%1}, [%4];\n\t"
        "@!p ld.global.nc.v2.f32 {%0,%1}, [%5];\n\t"
        "}"
        : "=f"(r.x), "=f"(r.y)
        : "r"(e), "n"(SMEM_ENTRIES), "r"(saddr), "l"(gaddr));
    return r;
}

__global__ void __launch_bounds__(NUM_THREADS, 1)
bitshift_lut_hybrid_kernel(const float2* __restrict__ lut,
                           const int4*  __restrict__ enc,
                           float4* __restrict__ out0,
                           float4* __restrict__ out1)
{
    extern __shared__ float2 lut_s[];

    // Fill the SMEM-resident slice of the LUT (coalesced, L2-hot after wave 1).
    #pragma unroll 4
    for (int i = threadIdx.x; i < SMEM_ENTRIES; i += NUM_THREADS)
        lut_s[i] = __ldg(&lut[i]);
    __syncthreads();

    uint32_t smem_base;
    asm("{ .reg .u64 t; cvta.to.shared.u64 t, %1; cvt.u32.u64 %0, t; }"
        : "=r"(smem_base) : "l"(lut_s));

    const long long stride = (long long)NUM_CTAS * NUM_THREADS;
    for (long long i = (long long)blockIdx.x * NUM_THREADS + threadIdx.x;
         i < TOTAL4; i += stride)
    {
        int4 e = enc[i];

        float2 a = gather_lut(e.x, smem_base, lut);
        float2 b = gather_lut(e.y, smem_base, lut);
        float2 c = gather_lut(e.z, smem_base, lut);
        float2 d = gather_lut(e.w, smem_base, lut);

        out0[i] = make_float4(a.x, b.x, c.x, d.x);   // plane v=0
        out1[i] = make_float4(a.y, b.y, c.y, d.y);   // plane v=1
    }
}

extern "C" void kernel_launch(void* const* d_in, const int* in_sizes, int n_in,
                              void* d_out, int out_size)
{
    const float2* lut = (const float2*)d_in[0];   // tlut (65536, 2)
    const int4*   enc = (const int4*)d_in[1];     // encoded (128, 262144)
    float* out = (float*)d_out;                   // (2, 128, 262144)

    float4* out0 = (float4*)out;
    float4* out1 = (float4*)(out + TOTAL);

    cudaFuncSetAttribute(bitshift_lut_hybrid_kernel,
                         cudaFuncAttributeMaxDynamicSharedMemorySize, SMEM_BYTES);

    bitshift_lut_hybrid_kernel<<<NUM_CTAS, NUM_THREADS, SMEM_BYTES>>>(
        lut, enc, out0, out1);
}

// round 4
// speedup vs baseline: 1.3115x; 1.3115x over previous
#include <cuda_runtime.h>
#include <cuda_bf16.h>
#include <cstdint>

// out[v, t, n] = tlut[encoded[t, n], v]
// tlut:   (65536, 2) float32 -> contiguous float2 per entry (8B)
// encoded:(128, 262144) int32
// out:    (2, 128, 262144) float32
//
// L1tex-wavefront-bound random gather (irreducible ~1 wf per gather).
// R1 structure + two tweaks:
//  - enc loads via __ldcg (L2-only): don't thrash L1D holding the LUT
//  - 8 gathers in flight per thread (2 quads) to saturate wf issue

static constexpr long long TB_ = 128;
static constexpr long long N_  = 262144;
static constexpr long long TOTAL  = TB_ * N_;      // 33,554,432 per plane
static constexpr long long TOTAL4 = TOTAL / 4;     // 8,388,608 quads
static constexpr int QUADS_PER_THREAD = 2;

__global__ void __launch_bounds__(256, 8)
bitshift_lut_gather_kernel(const float2* __restrict__ lut,
                           const int4*  __restrict__ enc,
                           float4* __restrict__ out0,
                           float4* __restrict__ out1)
{
    // Block covers 512 consecutive quads; thread t handles quads base+t and
    // base+t+256 -> every access fully coalesced.
    long long base = (long long)blockIdx.x * (256 * QUADS_PER_THREAD) + threadIdx.x;

    // Streaming index loads: L2-only, keep L1D for the LUT.
    int4 e0 = __ldcg(&enc[base]);
    int4 e1 = __ldcg(&enc[base + 256]);

    // 8 independent 8B gathers in flight (high MLP through L1/L2 latency).
    float2 a0 = __ldg(&lut[e0.x]);
    float2 b0 = __ldg(&lut[e0.y]);
    float2 c0 = __ldg(&lut[e0.z]);
    float2 d0 = __ldg(&lut[e0.w]);
    float2 a1 = __ldg(&lut[e1.x]);
    float2 b1 = __ldg(&lut[e1.y]);
    float2 c1 = __ldg(&lut[e1.z]);
    float2 d1 = __ldg(&lut[e1.w]);

    out0[base]       = make_float4(a0.x, b0.x, c0.x, d0.x);  // plane v=0
    out1[base]       = make_float4(a0.y, b0.y, c0.y, d0.y);  // plane v=1
    out0[base + 256] = make_float4(a1.x, b1.x, c1.x, d1.x);
    out1[base + 256] = make_float4(a1.y, b1.y, c1.y, d1.y);
}

extern "C" void kernel_launch(void* const* d_in, const int* in_sizes, int n_in,
                              void* d_out, int out_size)
{
    const float2* lut = (const float2*)d_in[0];   // tlut (65536, 2)
    const int4*   enc = (const int4*)d_in[1];     // encoded (128, 262144)
    float* out = (float*)d_out;                   // (2, 128, 262144)

    float4* out0 = (float4*)out;
    float4* out1 = (float4*)(out + TOTAL);

    const int threads = 256;
    const long long quads_per_block = threads * QUADS_PER_THREAD;   // 512
    const int blocks = (int)(TOTAL4 / quads_per_block);             // 16384 exact
    bitshift_lut_gather_kernel<<<blocks, threads>>>(lut, enc, out0, out1);
}